// round 1
// baseline (speedup 1.0000x reference)
#include <cuda_runtime.h>
#include <cstdint>

// Problem constants
#define T_SEQ 200
#define BATCH 1024
#define EMB   128
#define HID   128
#define G3    384          // 3*HID, gate order r,z,n
#define NROWS (BATCH * T_SEQ)

// 314 MB scratch for gx = x @ W_ih^T + b_ih  (static __device__: allocation-free)
__device__ float g_gx[(size_t)NROWS * G3];

// ---------------------------------------------------------------------------
// Kernel 1: fused embedding gather + input-side GEMM
//   gx[row, g] = sum_e emb[seq[row], e] * W_ih[g, e] + b_ih[g]
//   row = b*T_SEQ + t  (row-major over [B,T])
// CTA tile: 64 rows x 128 cols. W tile stored k-major in SMEM (transposed).
// ---------------------------------------------------------------------------
#define RM    64
#define XPAD  132
#define WPAD  132
#define SM1_BYTES ((RM * XPAD + 128 * WPAD) * 4)

__global__ __launch_bounds__(256) void gx_kernel(
    const int*   __restrict__ seq,
    const float* __restrict__ emb,
    const float* __restrict__ Wih,
    const float* __restrict__ bih)
{
    extern __shared__ float sm[];
    float* xs = sm;                  // [RM][XPAD]  x tile, row-major
    float* ws = sm + RM * XPAD;      // [128][WPAD] W tile, k-major: ws[k][c]

    const int t    = threadIdx.x;
    const int row0 = blockIdx.x * RM;
    const int c0   = blockIdx.y * 128;

    // ---- load x tile (gather from embedding table) ----
    {
        int r  = t >> 2;             // 64 rows, 4 threads per row
        int k0 = (t & 3) * 32;       // each thread loads 32 contiguous floats
        int idx = __ldg(seq + row0 + r);
        const float4* src = (const float4*)(emb + (size_t)idx * EMB + k0);
        float4* dst = (float4*)(xs + r * XPAD + k0);
        #pragma unroll
        for (int i = 0; i < 8; i++) dst[i] = src[i];
    }
    // ---- load W tile, transposed to k-major ----
    {
        #pragma unroll
        for (int i = 0; i < 16; i++) {
            int flat = t + 256 * i;          // 4096 float4s = 128 c x 32 k4
            int c  = flat & 127;
            int k4 = (flat >> 7) << 2;
            float4 w = *(const float4*)(Wih + (size_t)(c0 + c) * EMB + k4);
            ws[(k4 + 0) * WPAD + c] = w.x;
            ws[(k4 + 1) * WPAD + c] = w.y;
            ws[(k4 + 2) * WPAD + c] = w.z;
            ws[(k4 + 3) * WPAD + c] = w.w;
        }
    }
    __syncthreads();

    // ---- compute: thread tile 8 rows x 4 cols ----
    const int rg = t >> 5;           // 8 row-groups of 8 rows (warp-uniform -> smem broadcast)
    const int cg = t & 31;           // 32 col-groups of 4 cols
    float acc[8][4];
    #pragma unroll
    for (int r = 0; r < 8; r++) { acc[r][0]=0.f; acc[r][1]=0.f; acc[r][2]=0.f; acc[r][3]=0.f; }

    const float* xbase = xs + (rg * 8) * XPAD;
    const float* wbase = ws + cg * 4;

    #pragma unroll 4
    for (int k = 0; k < 128; k += 4) {
        float4 w0 = *(const float4*)(wbase + (k + 0) * WPAD);
        float4 w1 = *(const float4*)(wbase + (k + 1) * WPAD);
        float4 w2 = *(const float4*)(wbase + (k + 2) * WPAD);
        float4 w3 = *(const float4*)(wbase + (k + 3) * WPAD);
        #pragma unroll
        for (int r = 0; r < 8; r++) {
            float4 xv = *(const float4*)(xbase + r * XPAD + k);
            acc[r][0] += xv.x * w0.x + xv.y * w1.x + xv.z * w2.x + xv.w * w3.x;
            acc[r][1] += xv.x * w0.y + xv.y * w1.y + xv.z * w2.y + xv.w * w3.y;
            acc[r][2] += xv.x * w0.z + xv.y * w1.z + xv.z * w2.z + xv.w * w3.z;
            acc[r][3] += xv.x * w0.w + xv.y * w1.w + xv.z * w2.w + xv.w * w3.w;
        }
    }

    // ---- epilogue: + bias, store float4 ----
    float4 bv = *(const float4*)(bih + c0 + cg * 4);
    #pragma unroll
    for (int r = 0; r < 8; r++) {
        int row = row0 + rg * 8 + r;
        float4 o;
        o.x = acc[r][0] + bv.x;
        o.y = acc[r][1] + bv.y;
        o.z = acc[r][2] + bv.z;
        o.w = acc[r][3] + bv.w;
        *(float4*)(g_gx + (size_t)row * G3 + c0 + cg * 4) = o;
    }
}

// ---------------------------------------------------------------------------
// Kernel 2: GRU recurrence. Each CTA owns 8 batch rows for all 200 steps.
// W_hh resident in SMEM (g-major, padded). h resident in SMEM.
// Per step: phase 1 = gh = h @ W_hh^T + b_hh (register-tiled 4 rows x 3 gates
// per thread), phase 2 = gates + h update. gx for the step is prefetched into
// registers before phase 1 so its global latency hides under the GEMM.
// ---------------------------------------------------------------------------
#define BM     8
#define KPAD   132
#define GHPAD  388
#define SM2_BYTES ((G3 * KPAD + BM * KPAD + BM * GHPAD + G3) * 4)

__device__ __forceinline__ float fsigmoid(float x) {
    return __fdividef(1.f, 1.f + __expf(-x));
}

__global__ __launch_bounds__(256) void gru_kernel(
    const float* __restrict__ Whh,
    const float* __restrict__ bhh,
    float*       __restrict__ out)
{
    extern __shared__ float sm[];
    float* ws  = sm;                          // [G3][KPAD]  W_hh, g-major
    float* hs  = ws + G3 * KPAD;              // [BM][KPAD]  hidden state
    float* ghs = hs + BM * KPAD;              // [BM][GHPAD] gh scratch
    float* bhs = ghs + BM * GHPAD;            // [G3]        b_hh

    const int t  = threadIdx.x;
    const int b0 = blockIdx.x * BM;

    // ---- load W_hh into SMEM ----
    #pragma unroll
    for (int i = 0; i < 48; i++) {
        int flat = t + 256 * i;               // 12288 float4s = 384 g x 32 k4
        int g  = flat >> 5;
        int k4 = (flat & 31) << 2;
        float4 w = *(const float4*)(Whh + (size_t)g * HID + k4);
        *(float4*)(ws + g * KPAD + k4) = w;
    }
    if (t < 128) {
        bhs[t]       = bhh[t];
        bhs[t + 128] = bhh[t + 128];
        bhs[t + 256] = bhh[t + 256];
    }
    // ---- h = 0 ----
    #pragma unroll
    for (int p = 0; p < 4; p++) {
        int pos = t + 256 * p;
        hs[(pos >> 7) * KPAD + (pos & 127)] = 0.f;
    }
    __syncthreads();

    // phase-1 mapping: thread -> (row group rg of 4 rows, 3 consecutive gates)
    const int gg = t >> 1;                    // 0..127
    const int rg = t & 1;                     // 0..1
    const int g0 = gg * 3;
    const float* wp0 = ws + (g0 + 0) * KPAD;
    const float* wp1 = ws + (g0 + 1) * KPAD;
    const float* wp2 = ws + (g0 + 2) * KPAD;
    const float* hp  = hs + (rg * 4) * KPAD;
    const float bb0 = bhs[g0], bb1 = bhs[g0 + 1], bb2 = bhs[g0 + 2];

    // phase-2 mapping: 4 (row,k) positions per thread, coalesced in k
    int pr[4], pk[4];
    #pragma unroll
    for (int p = 0; p < 4; p++) { int pos = t + 256 * p; pr[p] = pos >> 7; pk[p] = pos & 127; }

    for (int ts = 0; ts < T_SEQ; ts++) {
        // ---- prefetch this step's gx into registers (hidden under GEMM) ----
        float xr[4], xz[4], xn[4];
        #pragma unroll
        for (int p = 0; p < 4; p++) {
            const float* gp = g_gx + ((size_t)(b0 + pr[p]) * T_SEQ + ts) * G3 + pk[p];
            xr[p] = __ldg(gp);
            xz[p] = __ldg(gp + 128);
            xn[p] = __ldg(gp + 256);
        }

        // ---- phase 1: gh = h @ W_hh^T + b_hh ----
        float a0[4], a1[4], a2[4];
        #pragma unroll
        for (int r = 0; r < 4; r++) { a0[r] = bb0; a1[r] = bb1; a2[r] = bb2; }

        #pragma unroll 4
        for (int k = 0; k < 128; k += 4) {
            float4 w0 = *(const float4*)(wp0 + k);
            float4 w1 = *(const float4*)(wp1 + k);
            float4 w2 = *(const float4*)(wp2 + k);
            #pragma unroll
            for (int r = 0; r < 4; r++) {
                float4 hv = *(const float4*)(hp + r * KPAD + k);
                a0[r] += hv.x * w0.x + hv.y * w0.y + hv.z * w0.z + hv.w * w0.w;
                a1[r] += hv.x * w1.x + hv.y * w1.y + hv.z * w1.z + hv.w * w1.w;
                a2[r] += hv.x * w2.x + hv.y * w2.y + hv.z * w2.z + hv.w * w2.w;
            }
        }
        #pragma unroll
        for (int r = 0; r < 4; r++) {
            int row = rg * 4 + r;
            ghs[row * GHPAD + g0 + 0] = a0[r];
            ghs[row * GHPAD + g0 + 1] = a1[r];
            ghs[row * GHPAD + g0 + 2] = a2[r];
        }
        __syncthreads();

        // ---- phase 2: gates + hidden update ----
        #pragma unroll
        for (int p = 0; p < 4; p++) {
            int r = pr[p], k = pk[p];
            float hrv = ghs[r * GHPAD + k];
            float hzv = ghs[r * GHPAD + 128 + k];
            float hnv = ghs[r * GHPAD + 256 + k];
            float hprev = hs[r * KPAD + k];
            float rr = fsigmoid(xr[p] + hrv);
            float zz = fsigmoid(xz[p] + hzv);
            float narg = xn[p] + rr * hnv;
            float nn = 2.f * fsigmoid(2.f * narg) - 1.f;   // tanh
            hs[r * KPAD + k] = (1.f - zz) * nn + zz * hprev;
        }
        __syncthreads();
    }

    // ---- write final hidden state ----
    #pragma unroll
    for (int p = 0; p < 4; p++) {
        out[(size_t)(b0 + pr[p]) * HID + pk[p]] = hs[pr[p] * KPAD + pk[p]];
    }
}

// ---------------------------------------------------------------------------
// Launch
// ---------------------------------------------------------------------------
extern "C" void kernel_launch(void* const* d_in, const int* in_sizes, int n_in,
                              void* d_out, int out_size)
{
    const int*   seq = (const int*)  d_in[0];  // [1024, 200] int32
    const float* emb = (const float*)d_in[1];  // [100000, 128]
    const float* Wih = (const float*)d_in[2];  // [384, 128]
    const float* Whh = (const float*)d_in[3];  // [384, 128]
    const float* bih = (const float*)d_in[4];  // [384]
    const float* bhh = (const float*)d_in[5];  // [384]
    float* out = (float*)d_out;                // [1024, 128]

    cudaFuncSetAttribute(gx_kernel,  cudaFuncAttributeMaxDynamicSharedMemorySize, SM1_BYTES);
    cudaFuncSetAttribute(gru_kernel, cudaFuncAttributeMaxDynamicSharedMemorySize, SM2_BYTES);

    dim3 grid1(NROWS / RM, G3 / 128);          // 3200 x 3
    gx_kernel<<<grid1, 256, SM1_BYTES>>>(seq, emb, Wih, bih);

    gru_kernel<<<BATCH / BM, 256, SM2_BYTES>>>(Whh, bhh, out);
}

// round 2
// speedup vs baseline: 1.1715x; 1.1715x over previous
#include <cuda_runtime.h>
#include <cstdint>

// Problem constants
#define T_SEQ 200
#define BATCH 1024
#define EMB   128
#define HID   128
#define G3    384          // 3*HID, gate order r,z,n
#define NROWS (BATCH * T_SEQ)

// 314 MB scratch for gx = x @ W_ih^T + b_ih  (static __device__: allocation-free)
__device__ float g_gx[(size_t)NROWS * G3];

// Packed fp32x2 FMA: d.lo += a.lo*b.lo ; d.hi += a.hi*b.hi  (one issue slot, 2 FMAs)
__device__ __forceinline__ void fma2(unsigned long long& d,
                                     unsigned long long a,
                                     unsigned long long b) {
    asm("fma.rn.f32x2 %0, %1, %2, %0;" : "+l"(d) : "l"(a), "l"(b));
}
__device__ __forceinline__ float pairsum(unsigned long long d) {
    float lo = __uint_as_float((unsigned)(d & 0xffffffffULL));
    float hi = __uint_as_float((unsigned)(d >> 32));
    return lo + hi;
}

// ---------------------------------------------------------------------------
// Kernel 1: fused embedding gather + input-side GEMM
//   gx[row, g] = sum_e emb[seq[row], e] * W_ih[g, e] + b_ih[g]
// CTA tile 64 rows x 128 cols. Both x and W kept k-major in SMEM so each
// float4 load yields two ready-made f32x2 operands (pack along K).
// Thread tile: 8 rows x 4 cols, cols strided by 32 for conflict-free LDS.128.
// ---------------------------------------------------------------------------
#define RM    64
#define XPAD  132          // 33 float4s per row: odd pitch -> conflict-free
#define SM1_BYTES ((RM * XPAD + 128 * XPAD) * 4)

__global__ __launch_bounds__(256) void gx_kernel(
    const int*   __restrict__ seq,
    const float* __restrict__ emb,
    const float* __restrict__ Wih,
    const float* __restrict__ bih)
{
    extern __shared__ float sm[];
    float* xs = sm;                  // [RM][XPAD]   x tile, k-major
    float* ws = sm + RM * XPAD;      // [128][XPAD]  W tile, k-major (NOT transposed)

    const int t    = threadIdx.x;
    const int row0 = blockIdx.x * RM;
    const int c0   = blockIdx.y * 128;

    // ---- load x tile (gather from embedding table) ----
    {
        int r  = t >> 2;             // 64 rows, 4 threads per row
        int k0 = (t & 3) * 32;
        int idx = __ldg(seq + row0 + r);
        const float4* src = (const float4*)(emb + (size_t)idx * EMB + k0);
        float4* dst = (float4*)(xs + r * XPAD + k0);
        #pragma unroll
        for (int i = 0; i < 8; i++) dst[i] = src[i];
    }
    // ---- load W tile (direct row copy, k-major) ----
    {
        #pragma unroll
        for (int i = 0; i < 16; i++) {
            int flat = t + 256 * i;          // 4096 float4s = 128 c x 32 k4
            int c  = flat >> 5;
            int k4 = (flat & 31) << 2;
            *(float4*)(ws + c * XPAD + k4) =
                *(const float4*)(Wih + (size_t)(c0 + c) * EMB + k4);
        }
    }
    __syncthreads();

    // ---- compute: 8 rows x 4 cols per thread, f32x2-packed along K ----
    const int rg = t >> 5;           // warp-uniform row group -> x loads broadcast
    const int cg = t & 31;           // cols: cg, cg+32, cg+64, cg+96
    unsigned long long acc[8][4];
    #pragma unroll
    for (int r = 0; r < 8; r++)
        #pragma unroll
        for (int j = 0; j < 4; j++) acc[r][j] = 0ULL;

    const float* xbase = xs + (rg * 8) * XPAD;

    #pragma unroll 4
    for (int k = 0; k < 128; k += 4) {
        ulonglong2 wv[4];
        #pragma unroll
        for (int j = 0; j < 4; j++)
            wv[j] = *(const ulonglong2*)(ws + (cg + 32 * j) * XPAD + k);
        #pragma unroll
        for (int r = 0; r < 8; r++) {
            ulonglong2 xv = *(const ulonglong2*)(xbase + r * XPAD + k);
            #pragma unroll
            for (int j = 0; j < 4; j++) {
                fma2(acc[r][j], xv.x, wv[j].x);
                fma2(acc[r][j], xv.y, wv[j].y);
            }
        }
    }

    // ---- epilogue: reduce pairs, + bias, scalar stores (coalesced over cg) ----
    #pragma unroll
    for (int j = 0; j < 4; j++) {
        int c = c0 + cg + 32 * j;
        float bv = __ldg(bih + c);
        #pragma unroll
        for (int r = 0; r < 8; r++) {
            int row = row0 + rg * 8 + r;
            g_gx[(size_t)row * G3 + c] = pairsum(acc[r][j]) + bv;
        }
    }
}

// ---------------------------------------------------------------------------
// Kernel 2: GRU recurrence. Each CTA owns 8 batch rows for all 200 steps.
// W_hh (fp32, g-major/k-contiguous) + h resident in SMEM.
// Phase 1 GEMM uses f32x2 packed along K: per thread 3 gates x 4 rows.
// ---------------------------------------------------------------------------
#define BM     8
#define KPAD   132
#define GHPAD  388
#define SM2_BYTES ((G3 * KPAD + BM * KPAD + BM * GHPAD + G3) * 4)

__device__ __forceinline__ float fsigmoid(float x) {
    return __fdividef(1.f, 1.f + __expf(-x));
}

__global__ __launch_bounds__(256) void gru_kernel(
    const float* __restrict__ Whh,
    const float* __restrict__ bhh,
    float*       __restrict__ out)
{
    extern __shared__ float sm[];
    float* ws  = sm;                          // [G3][KPAD]  W_hh, k-contiguous
    float* hs  = ws + G3 * KPAD;              // [BM][KPAD]  hidden state
    float* ghs = hs + BM * KPAD;              // [BM][GHPAD] gh scratch
    float* bhs = ghs + BM * GHPAD;            // [G3]        b_hh

    const int t  = threadIdx.x;
    const int b0 = blockIdx.x * BM;

    // ---- load W_hh into SMEM ----
    #pragma unroll
    for (int i = 0; i < 48; i++) {
        int flat = t + 256 * i;               // 12288 float4s = 384 g x 32 k4
        int g  = flat >> 5;
        int k4 = (flat & 31) << 2;
        *(float4*)(ws + g * KPAD + k4) = *(const float4*)(Whh + (size_t)g * HID + k4);
    }
    if (t < 128) {
        bhs[t]       = bhh[t];
        bhs[t + 128] = bhh[t + 128];
        bhs[t + 256] = bhh[t + 256];
    }
    // ---- h = 0 ----
    #pragma unroll
    for (int p = 0; p < 4; p++) {
        int pos = t + 256 * p;
        hs[(pos >> 7) * KPAD + (pos & 127)] = 0.f;
    }
    __syncthreads();

    // phase-1 mapping: thread -> (row group of 4 rows, 3 consecutive gates)
    const int gg = t >> 1;                    // 0..127
    const int rg = t & 1;                     // 0..1
    const int g0 = gg * 3;
    const float* wp0 = ws + (g0 + 0) * KPAD;
    const float* wp1 = ws + (g0 + 1) * KPAD;
    const float* wp2 = ws + (g0 + 2) * KPAD;
    const float* hp  = hs + (rg * 4) * KPAD;
    const float bb0 = bhs[g0], bb1 = bhs[g0 + 1], bb2 = bhs[g0 + 2];

    // phase-2 mapping: 4 (row,k) positions per thread, coalesced in k
    int pr[4], pk[4];
    #pragma unroll
    for (int p = 0; p < 4; p++) { int pos = t + 256 * p; pr[p] = pos >> 7; pk[p] = pos & 127; }

    for (int ts = 0; ts < T_SEQ; ts++) {
        // ---- prefetch this step's gx into registers (hidden under GEMM) ----
        float xr[4], xz[4], xn[4];
        #pragma unroll
        for (int p = 0; p < 4; p++) {
            const float* gp = g_gx + ((size_t)(b0 + pr[p]) * T_SEQ + ts) * G3 + pk[p];
            xr[p] = __ldg(gp);
            xz[p] = __ldg(gp + 128);
            xn[p] = __ldg(gp + 256);
        }

        // ---- phase 1: gh = h @ W_hh^T + b_hh  (f32x2 packed along K) ----
        unsigned long long a0[4], a1[4], a2[4];
        #pragma unroll
        for (int r = 0; r < 4; r++) {
            a0[r] = (unsigned long long)__float_as_uint(bb0);   // lo=bias, hi=0
            a1[r] = (unsigned long long)__float_as_uint(bb1);
            a2[r] = (unsigned long long)__float_as_uint(bb2);
        }

        #pragma unroll 4
        for (int k = 0; k < 128; k += 4) {
            ulonglong2 w0 = *(const ulonglong2*)(wp0 + k);
            ulonglong2 w1 = *(const ulonglong2*)(wp1 + k);
            ulonglong2 w2 = *(const ulonglong2*)(wp2 + k);
            #pragma unroll
            for (int r = 0; r < 4; r++) {
                ulonglong2 hv = *(const ulonglong2*)(hp + r * KPAD + k);
                fma2(a0[r], hv.x, w0.x);  fma2(a0[r], hv.y, w0.y);
                fma2(a1[r], hv.x, w1.x);  fma2(a1[r], hv.y, w1.y);
                fma2(a2[r], hv.x, w2.x);  fma2(a2[r], hv.y, w2.y);
            }
        }
        #pragma unroll
        for (int r = 0; r < 4; r++) {
            int row = rg * 4 + r;
            ghs[row * GHPAD + g0 + 0] = pairsum(a0[r]);
            ghs[row * GHPAD + g0 + 1] = pairsum(a1[r]);
            ghs[row * GHPAD + g0 + 2] = pairsum(a2[r]);
        }
        __syncthreads();

        // ---- phase 2: gates + hidden update ----
        #pragma unroll
        for (int p = 0; p < 4; p++) {
            int r = pr[p], k = pk[p];
            float hrv = ghs[r * GHPAD + k];
            float hzv = ghs[r * GHPAD + 128 + k];
            float hnv = ghs[r * GHPAD + 256 + k];
            float hprev = hs[r * KPAD + k];
            float rr = fsigmoid(xr[p] + hrv);
            float zz = fsigmoid(xz[p] + hzv);
            float narg = xn[p] + rr * hnv;
            float nn = 2.f * fsigmoid(2.f * narg) - 1.f;   // tanh
            hs[r * KPAD + k] = (1.f - zz) * nn + zz * hprev;
        }
        __syncthreads();
    }

    // ---- write final hidden state ----
    #pragma unroll
    for (int p = 0; p < 4; p++) {
        out[(size_t)(b0 + pr[p]) * HID + pk[p]] = hs[pr[p] * KPAD + pk[p]];
    }
}

// ---------------------------------------------------------------------------
// Launch
// ---------------------------------------------------------------------------
extern "C" void kernel_launch(void* const* d_in, const int* in_sizes, int n_in,
                              void* d_out, int out_size)
{
    const int*   seq = (const int*)  d_in[0];  // [1024, 200] int32
    const float* emb = (const float*)d_in[1];  // [100000, 128]
    const float* Wih = (const float*)d_in[2];  // [384, 128]
    const float* Whh = (const float*)d_in[3];  // [384, 128]
    const float* bih = (const float*)d_in[4];  // [384]
    const float* bhh = (const float*)d_in[5];  // [384]
    float* out = (float*)d_out;                // [1024, 128]

    cudaFuncSetAttribute(gx_kernel,  cudaFuncAttributeMaxDynamicSharedMemorySize, SM1_BYTES);
    cudaFuncSetAttribute(gru_kernel, cudaFuncAttributeMaxDynamicSharedMemorySize, SM2_BYTES);

    dim3 grid1(NROWS / RM, G3 / 128);          // 3200 x 3
    gx_kernel<<<grid1, 256, SM1_BYTES>>>(seq, emb, Wih, bih);

    gru_kernel<<<BATCH / BM, 256, SM2_BYTES>>>(Whh, bhh, out);
}